// round 4
// baseline (speedup 1.0000x reference)
#include <cuda_runtime.h>
#include <cstdint>

#define N_NODES 100000
#define N_EDGES 1600000
#define N_GRAPHS 2048
#define D 128
#define DFC 256
#define DOUT 8

#define SCAN_CHUNK 1024
#define SCAN_NB ((N_NODES + SCAN_CHUNK - 1) / SCAN_CHUNK)   // 98

#define GB_GATHER 12500          // 8 nodes per block (warp per node, 256 thr)
#define GB_GEMM   782            // 128 rows per block
#define GB_TOTAL  (17 * GB_GEMM) // interleave 16 gather : 1 gemm

// ---------------- scratch (static device globals; no allocation) ----------------
__device__ float g_agg[(size_t)N_NODES * D];
__device__ float g_tmp[(size_t)N_NODES * D];
__device__ float g_hA[(size_t)N_NODES * D];
__device__ float g_hB[(size_t)N_NODES * D];
__device__ float g_pool[(size_t)N_GRAPHS * D];
__device__ float g_fc1[(size_t)N_GRAPHS * DFC];
__device__ int   g_src[N_EDGES];
__device__ int   g_dst[N_EDGES];
__device__ int   g_batch[N_NODES];
__device__ int   g_counts[N_NODES];          // zeroed by cudaMemsetAsync
__device__ int   g_row_ptr[N_NODES + 1];
__device__ int   g_cursor[N_NODES];
__device__ int   g_csr_src[N_EDGES];
__device__ int   g_blocksum[SCAN_NB];

// selector: 0 -> external x, 1 -> g_hA, 2 -> g_hB
__device__ __forceinline__ const float* pick_in(const float* x, int sel) {
    return sel == 0 ? x : (sel == 1 ? g_hA : g_hB);
}
__device__ __forceinline__ float* pick_out(int sel) {
    return sel == 1 ? g_hA : g_hB;
}

// ---------------- convert indices (self-detecting dtype) + per-dst counts ----------------
__device__ __forceinline__ int detect_is64(const void* ei) {
    const long long* p64 = (const long long*)ei;
    int ok = 1;
    #pragma unroll
    for (int i = 0; i < 16; i++) {
        long long v = __ldg(&p64[i]);
        if (v < 0 || v >= N_NODES) ok = 0;
    }
    return ok;
}

__global__ void convert_count_kernel(const void* ei, const void* batch) {
    int i = blockIdx.x * blockDim.x + threadIdx.x;
    int is64 = detect_is64(ei);
    if (i < N_EDGES) {
        int s, d;
        if (is64) {
            const long long* p = (const long long*)ei;
            s = (int)__ldg(&p[i]);
            d = (int)__ldg(&p[(size_t)N_EDGES + i]);
        } else {
            const int* p = (const int*)ei;
            s = __ldg(&p[i]);
            d = __ldg(&p[N_EDGES + i]);
        }
        g_src[i] = s;
        g_dst[i] = d;
        atomicAdd(&g_counts[d], 1);
    }
    if (i < N_NODES) {
        if (is64) g_batch[i] = (int)__ldg(&((const long long*)batch)[i]);
        else      g_batch[i] = __ldg(&((const int*)batch)[i]);
    }
}

// ---------------- scan: counts -> row_ptr (exclusive) ----------------
__global__ void scan1_kernel() {
    __shared__ int sh[256];
    int b = blockIdx.x, t = threadIdx.x;
    int i0 = b * SCAN_CHUNK + t * 4;
    int s = 0;
    #pragma unroll
    for (int j = 0; j < 4; j++) {
        int i = i0 + j;
        if (i < N_NODES) s += g_counts[i];
    }
    sh[t] = s;
    __syncthreads();
    for (int off = 128; off > 0; off >>= 1) {
        if (t < off) sh[t] += sh[t + off];
        __syncthreads();
    }
    if (t == 0) g_blocksum[b] = sh[0];
}

__global__ void scan2_kernel() {
    if (threadIdx.x == 0 && blockIdx.x == 0) {
        int run = 0;
        for (int b = 0; b < SCAN_NB; b++) {
            int v = g_blocksum[b];
            g_blocksum[b] = run;
            run += v;
        }
        g_row_ptr[N_NODES] = run;
    }
}

__global__ void scan3_kernel() {
    __shared__ int sh[256];
    int b = blockIdx.x, t = threadIdx.x;
    int i0 = b * SCAN_CHUNK + t * 4;
    int c[4];
    int tsum = 0;
    #pragma unroll
    for (int j = 0; j < 4; j++) {
        int i = i0 + j;
        c[j] = (i < N_NODES) ? g_counts[i] : 0;
        tsum += c[j];
    }
    sh[t] = tsum;
    __syncthreads();
    #pragma unroll
    for (int off = 1; off < 256; off <<= 1) {
        int v = (t >= off) ? sh[t - off] : 0;
        __syncthreads();
        sh[t] += v;
        __syncthreads();
    }
    int base = g_blocksum[b] + sh[t] - tsum;
    #pragma unroll
    for (int j = 0; j < 4; j++) {
        int i = i0 + j;
        if (i < N_NODES) {
            g_row_ptr[i] = base;
            g_cursor[i]  = base;
            base += c[j];
        }
    }
}

// ---------------- fill CSR ----------------
__global__ void fill_kernel() {
    int e = blockIdx.x * blockDim.x + threadIdx.x;
    if (e >= N_EDGES) return;
    int d = g_dst[e];
    int pos = atomicAdd(&g_cursor[d], 1);
    g_csr_src[pos] = g_src[e];
}

// ---------------- GEMM micro-kernel core (128x128x128, f32x2 accum) ----------------
// As: [128][16] staged per k0; Bs: [16][128]. acc: 8 rows x 4 col-pairs.
struct AccT { unsigned long long v[8][4]; };

__device__ __forceinline__ void gemm_tile(
    const float* __restrict__ A, const float* __restrict__ W,
    int m0, int tid, float* As, float* Bs, AccT& acc)
{
    int tx = tid & 15;
    int ty = tid >> 4;
    for (int k0 = 0; k0 < 128; k0 += 16) {
        #pragma unroll
        for (int i = 0; i < 2; i++) {
            int f = tid * 2 + i;
            int row = f >> 2;
            int c4 = f & 3;
            int gr = m0 + row;
            float4 v = make_float4(0.f, 0.f, 0.f, 0.f);
            if (gr < N_NODES)
                v = *reinterpret_cast<const float4*>(A + (size_t)gr * 128 + k0 + c4 * 4);
            *reinterpret_cast<float4*>(&As[row * 16 + c4 * 4]) = v;
        }
        #pragma unroll
        for (int i = 0; i < 2; i++) {
            int f = tid * 2 + i;
            int kr = f >> 5;
            int c4 = f & 31;
            float4 v = *reinterpret_cast<const float4*>(W + (size_t)(k0 + kr) * 128 + c4 * 4);
            *reinterpret_cast<float4*>(&Bs[kr * 128 + c4 * 4]) = v;
        }
        __syncthreads();

        #pragma unroll
        for (int k = 0; k < 16; k += 4) {
            float4 av[8];
            #pragma unroll
            for (int r = 0; r < 8; r++)
                av[r] = *reinterpret_cast<const float4*>(&As[(ty * 8 + r) * 16 + k]);
            #pragma unroll
            for (int kk = 0; kk < 4; kk++) {
                unsigned long long bb[4];
                const unsigned long long* Brow =
                    reinterpret_cast<const unsigned long long*>(&Bs[(k + kk) * 128]);
                #pragma unroll
                for (int j = 0; j < 4; j++) bb[j] = Brow[tx + 16 * j];
                #pragma unroll
                for (int r = 0; r < 8; r++) {
                    float a = (kk == 0) ? av[r].x : (kk == 1) ? av[r].y
                            : (kk == 2) ? av[r].z : av[r].w;
                    unsigned long long aa;
                    asm("mov.b64 %0,{%1,%2};" : "=l"(aa) : "f"(a), "f"(a));
                    #pragma unroll
                    for (int j = 0; j < 4; j++)
                        asm("fma.rn.f32x2 %0, %1, %2, %0;"
                            : "+l"(acc.v[r][j]) : "l"(aa), "l"(bb[j]));
                }
            }
        }
        __syncthreads();
    }
}

// ---------------- kernel A: gather blocks + root-GEMM blocks interleaved ----------------
// role gather: g_agg[node] = sum_{csr} hin[src]         (warp per node)
// role gemm:   g_tmp = hin @ Wroot + bias
__global__ __launch_bounds__(256) void layerA_kernel(
    const float* __restrict__ x, int sel_in,
    const float* __restrict__ Wroot, const float* __restrict__ bias)
{
    const float* hin = pick_in(x, sel_in);
    int bid = blockIdx.x;
    int r17 = bid % 17;
    int q17 = bid / 17;

    if (r17 < 16) {
        // ---- gather role ----
        int gather_id = q17 * 16 + r17;
        if (gather_id >= GB_GATHER) return;
        int wid = threadIdx.x >> 5;
        int lane = threadIdx.x & 31;
        int node = gather_id * 8 + wid;
        if (node >= N_NODES) return;
        const float4* h4 = reinterpret_cast<const float4*>(hin);
        int beg = g_row_ptr[node];
        int end = g_row_ptr[node + 1];
        float4 acc = make_float4(0.f, 0.f, 0.f, 0.f);
        int e = beg;
        for (; e + 4 <= end; e += 4) {
            int s0 = __ldg(&g_csr_src[e]);
            int s1 = __ldg(&g_csr_src[e + 1]);
            int s2 = __ldg(&g_csr_src[e + 2]);
            int s3 = __ldg(&g_csr_src[e + 3]);
            float4 v0 = __ldg(&h4[(size_t)s0 * 32 + lane]);
            float4 v1 = __ldg(&h4[(size_t)s1 * 32 + lane]);
            float4 v2 = __ldg(&h4[(size_t)s2 * 32 + lane]);
            float4 v3 = __ldg(&h4[(size_t)s3 * 32 + lane]);
            acc.x += v0.x + v1.x + v2.x + v3.x;
            acc.y += v0.y + v1.y + v2.y + v3.y;
            acc.z += v0.z + v1.z + v2.z + v3.z;
            acc.w += v0.w + v1.w + v2.w + v3.w;
        }
        for (; e < end; e++) {
            int s = __ldg(&g_csr_src[e]);
            float4 v = __ldg(&h4[(size_t)s * 32 + lane]);
            acc.x += v.x; acc.y += v.y; acc.z += v.z; acc.w += v.w;
        }
        reinterpret_cast<float4*>(g_agg)[(size_t)node * 32 + lane] = acc;
    } else {
        // ---- root-GEMM role ----
        __shared__ float As[128 * 16];
        __shared__ float Bs[16 * 128];
        int gemm_id = q17;
        if (gemm_id >= GB_GEMM) return;
        int m0 = gemm_id * 128;
        int tid = threadIdx.x;
        AccT acc;
        #pragma unroll
        for (int r = 0; r < 8; r++)
            #pragma unroll
            for (int j = 0; j < 4; j++) acc.v[r][j] = 0ULL;

        gemm_tile(hin, Wroot, m0, tid, As, Bs, acc);

        int tx = tid & 15;
        int ty = tid >> 4;
        #pragma unroll
        for (int r = 0; r < 8; r++) {
            int gr = m0 + ty * 8 + r;
            if (gr >= N_NODES) break;
            #pragma unroll
            for (int j = 0; j < 4; j++) {
                int p = tx + 16 * j;
                float2 v = *reinterpret_cast<float2*>(&acc.v[r][j]);
                v.x += bias[2 * p];
                v.y += bias[2 * p + 1];
                *reinterpret_cast<float2*>(&g_tmp[(size_t)gr * 128 + 2 * p]) = v;
            }
        }
    }
}

// ---------------- kernel B: hout = relu(g_agg @ Wrel + g_tmp) ----------------
__global__ __launch_bounds__(256) void layerB_kernel(
    int sel_out, const float* __restrict__ Wrel)
{
    __shared__ float As[128 * 16];
    __shared__ float Bs[16 * 128];
    float* hout = pick_out(sel_out);
    int m0 = blockIdx.x * 128;
    int tid = threadIdx.x;
    AccT acc;
    #pragma unroll
    for (int r = 0; r < 8; r++)
        #pragma unroll
        for (int j = 0; j < 4; j++) acc.v[r][j] = 0ULL;

    gemm_tile(g_agg, Wrel, m0, tid, As, Bs, acc);

    int tx = tid & 15;
    int ty = tid >> 4;
    #pragma unroll
    for (int r = 0; r < 8; r++) {
        int gr = m0 + ty * 8 + r;
        if (gr >= N_NODES) break;
        #pragma unroll
        for (int j = 0; j < 4; j++) {
            int p = tx + 16 * j;
            float2 t = *reinterpret_cast<const float2*>(&g_tmp[(size_t)gr * 128 + 2 * p]);
            float2 v = *reinterpret_cast<float2*>(&acc.v[r][j]);
            float lo = fmaxf(v.x + t.x, 0.f);
            float hi = fmaxf(v.y + t.y, 0.f);
            *reinterpret_cast<float2*>(&hout[(size_t)gr * 128 + 2 * p]) = make_float2(lo, hi);
        }
    }
}

// ---------------- pool: sorted-batch segments, block per graph, no atomics ----------------
__device__ __forceinline__ int lower_bound_batch(int v) {
    int lo = 0, hi = N_NODES;
    while (lo < hi) {
        int m = (lo + hi) >> 1;
        if (g_batch[m] < v) lo = m + 1; else hi = m;
    }
    return lo;
}

__global__ __launch_bounds__(128) void pool_kernel(const float* __restrict__ x, int sel_in) {
    int g = blockIdx.x;
    int t = threadIdx.x;
    const float* h = pick_in(x, sel_in);
    int lo = lower_bound_batch(g);
    int hi = lower_bound_batch(g + 1);
    float acc = 0.f;
    for (int n = lo; n < hi; n++)
        acc += __ldg(&h[(size_t)n * 128 + t]);
    float cnt = (float)(hi - lo);
    g_pool[(size_t)g * 128 + t] = acc / fmaxf(cnt, 1.0f);
}

// ---------------- fc1: 4 graphs per block ----------------
__global__ __launch_bounds__(256) void fc1_kernel(
    const float* __restrict__ w, const float* __restrict__ b)
{
    __shared__ float p[4][128];
    int g0 = blockIdx.x * 4;
    int t = threadIdx.x;
    #pragma unroll
    for (int i = 0; i < 2; i++) {
        int f = t + i * 256;
        p[f >> 7][f & 127] = g_pool[(size_t)g0 * 128 + f];
    }
    __syncthreads();
    float acc0 = b[t], acc1 = b[t], acc2 = b[t], acc3 = b[t];
    #pragma unroll 4
    for (int k = 0; k < 128; k++) {
        float wv = __ldg(&w[(size_t)k * 256 + t]);
        acc0 = fmaf(p[0][k], wv, acc0);
        acc1 = fmaf(p[1][k], wv, acc1);
        acc2 = fmaf(p[2][k], wv, acc2);
        acc3 = fmaf(p[3][k], wv, acc3);
    }
    g_fc1[(size_t)(g0 + 0) * 256 + t] = acc0;
    g_fc1[(size_t)(g0 + 1) * 256 + t] = acc1;
    g_fc1[(size_t)(g0 + 2) * 256 + t] = acc2;
    g_fc1[(size_t)(g0 + 3) * 256 + t] = acc3;
}

// ---------------- fc2 ----------------
__global__ void fc2_kernel(const float* __restrict__ w, const float* __restrict__ b,
                           float* __restrict__ out)
{
    int idx = blockIdx.x * blockDim.x + threadIdx.x;
    if (idx >= N_GRAPHS * DOUT) return;
    int g = idx >> 3, o = idx & 7;
    float acc = b[o];
    #pragma unroll 8
    for (int k = 0; k < 256; k++)
        acc = fmaf(g_fc1[(size_t)g * 256 + k], __ldg(&w[k * 8 + o]), acc);
    out[idx] = acc;
}

// ---------------- launch ----------------
extern "C" void kernel_launch(void* const* d_in, const int* in_sizes, int n_in,
                              void* d_out, int out_size)
{
    const float* x = (const float*)d_in[0];
    const void* ei = d_in[1];
    const void* batch = d_in[2];
    const float* Wrel[4]  = {(const float*)d_in[3], (const float*)d_in[6],
                             (const float*)d_in[9], (const float*)d_in[12]};
    const float* Wroot[4] = {(const float*)d_in[4], (const float*)d_in[7],
                             (const float*)d_in[10], (const float*)d_in[13]};
    const float* bias[4]  = {(const float*)d_in[5], (const float*)d_in[8],
                             (const float*)d_in[11], (const float*)d_in[14]};
    const float* fcw = (const float*)d_in[15];
    const float* fcb = (const float*)d_in[16];
    const float* regw = (const float*)d_in[17];
    const float* regb = (const float*)d_in[18];
    float* out = (float*)d_out;

    void* countsPtr = nullptr;
    cudaGetSymbolAddress(&countsPtr, g_counts);
    cudaMemsetAsync(countsPtr, 0, N_NODES * sizeof(int));

    // CSR build
    convert_count_kernel<<<(N_EDGES + 255) / 256, 256>>>(ei, batch);
    scan1_kernel<<<SCAN_NB, 256>>>();
    scan2_kernel<<<1, 32>>>();
    scan3_kernel<<<SCAN_NB, 256>>>();
    fill_kernel<<<(N_EDGES + 255) / 256, 256>>>();

    int ins[4]  = {0, 1, 2, 1};
    int outs[4] = {1, 2, 1, 2};
    for (int L = 0; L < 4; L++) {
        layerA_kernel<<<GB_TOTAL, 256>>>(x, ins[L], Wroot[L], bias[L]);
        layerB_kernel<<<GB_GEMM, 256>>>(outs[L], Wrel[L]);
    }

    pool_kernel<<<N_GRAPHS, 128>>>(x, 2);
    fc1_kernel<<<N_GRAPHS / 4, 256>>>(fcw, fcb);
    fc2_kernel<<<(N_GRAPHS * DOUT + 127) / 128, 128>>>(regw, regb, out);
}

// round 5
// speedup vs baseline: 1.6610x; 1.6610x over previous
#include <cuda_runtime.h>
#include <cstdint>

#define N_NODES 100000
#define N_EDGES 1600000
#define N_GRAPHS 2048
#define D 128
#define DFC 256
#define DOUT 8

#define SCAN_CHUNK 1024
#define SCAN_NB ((N_NODES + SCAN_CHUNK - 1) / SCAN_CHUNK)   // 98

// ---------------- scratch (static device globals; no allocation) ----------------
__device__ float g_agg[(size_t)N_NODES * D];
__device__ float g_tmp[(size_t)N_NODES * D];
__device__ float g_hA[(size_t)N_NODES * D];
__device__ float g_hB[(size_t)N_NODES * D];
__device__ float g_pool[(size_t)N_GRAPHS * D];
__device__ float g_fc1[(size_t)N_GRAPHS * DFC];
__device__ int   g_src[N_EDGES];
__device__ int   g_dst[N_EDGES];
__device__ int   g_batch[N_NODES];
__device__ int   g_counts[N_NODES];          // zeroed by cudaMemsetAsync
__device__ int   g_row_ptr[N_NODES + 1];
__device__ int   g_cursor[N_NODES];
__device__ int   g_csr_src[N_EDGES];
__device__ int   g_blocksum[SCAN_NB];

// selector: 0 -> external x, 1 -> g_hA, 2 -> g_hB
__device__ __forceinline__ const float* pick_in(const float* x, int sel) {
    return sel == 0 ? x : (sel == 1 ? g_hA : g_hB);
}
__device__ __forceinline__ float* pick_out(int sel) {
    return sel == 1 ? g_hA : g_hB;
}

// ---------------- convert indices (self-detecting dtype) + per-dst counts ----------------
__device__ __forceinline__ int detect_is64(const void* ei) {
    const long long* p64 = (const long long*)ei;
    int ok = 1;
    #pragma unroll
    for (int i = 0; i < 16; i++) {
        long long v = __ldg(&p64[i]);
        if (v < 0 || v >= N_NODES) ok = 0;
    }
    return ok;
}

__global__ void convert_count_kernel(const void* ei, const void* batch) {
    int i = blockIdx.x * blockDim.x + threadIdx.x;
    int is64 = detect_is64(ei);
    if (i < N_EDGES) {
        int s, d;
        if (is64) {
            const long long* p = (const long long*)ei;
            s = (int)__ldg(&p[i]);
            d = (int)__ldg(&p[(size_t)N_EDGES + i]);
        } else {
            const int* p = (const int*)ei;
            s = __ldg(&p[i]);
            d = __ldg(&p[N_EDGES + i]);
        }
        g_src[i] = s;
        g_dst[i] = d;
        atomicAdd(&g_counts[d], 1);
    }
    if (i < N_NODES) {
        if (is64) g_batch[i] = (int)__ldg(&((const long long*)batch)[i]);
        else      g_batch[i] = __ldg(&((const int*)batch)[i]);
    }
}

// ---------------- scan: counts -> row_ptr (exclusive) ----------------
__global__ void scan1_kernel() {
    __shared__ int sh[256];
    int b = blockIdx.x, t = threadIdx.x;
    int i0 = b * SCAN_CHUNK + t * 4;
    int s = 0;
    #pragma unroll
    for (int j = 0; j < 4; j++) {
        int i = i0 + j;
        if (i < N_NODES) s += g_counts[i];
    }
    sh[t] = s;
    __syncthreads();
    for (int off = 128; off > 0; off >>= 1) {
        if (t < off) sh[t] += sh[t + off];
        __syncthreads();
    }
    if (t == 0) g_blocksum[b] = sh[0];
}

__global__ void scan2_kernel() {
    if (threadIdx.x == 0 && blockIdx.x == 0) {
        int run = 0;
        for (int b = 0; b < SCAN_NB; b++) {
            int v = g_blocksum[b];
            g_blocksum[b] = run;
            run += v;
        }
        g_row_ptr[N_NODES] = run;
    }
}

__global__ void scan3_kernel() {
    __shared__ int sh[256];
    int b = blockIdx.x, t = threadIdx.x;
    int i0 = b * SCAN_CHUNK + t * 4;
    int c[4];
    int tsum = 0;
    #pragma unroll
    for (int j = 0; j < 4; j++) {
        int i = i0 + j;
        c[j] = (i < N_NODES) ? g_counts[i] : 0;
        tsum += c[j];
    }
    sh[t] = tsum;
    __syncthreads();
    #pragma unroll
    for (int off = 1; off < 256; off <<= 1) {
        int v = (t >= off) ? sh[t - off] : 0;
        __syncthreads();
        sh[t] += v;
        __syncthreads();
    }
    int base = g_blocksum[b] + sh[t] - tsum;
    #pragma unroll
    for (int j = 0; j < 4; j++) {
        int i = i0 + j;
        if (i < N_NODES) {
            g_row_ptr[i] = base;
            g_cursor[i]  = base;
            base += c[j];
        }
    }
}

// ---------------- fill CSR ----------------
__global__ void fill_kernel() {
    int e = blockIdx.x * blockDim.x + threadIdx.x;
    if (e >= N_EDGES) return;
    int d = g_dst[e];
    int pos = atomicAdd(&g_cursor[d], 1);
    g_csr_src[pos] = g_src[e];
}

// ---------------- gather (standalone, high-occupancy; R2-proven) ----------------
__global__ void gather_kernel(const float* __restrict__ x, int sel_in) {
    long long idx = (long long)blockIdx.x * blockDim.x + threadIdx.x;
    int node = (int)(idx >> 5);
    if (node >= N_NODES) return;
    int lane = (int)(idx & 31);
    const float* h = pick_in(x, sel_in);
    const float4* h4 = reinterpret_cast<const float4*>(h);
    int beg = g_row_ptr[node];
    int end = g_row_ptr[node + 1];
    float4 acc = make_float4(0.f, 0.f, 0.f, 0.f);
    int e = beg;
    for (; e + 4 <= end; e += 4) {
        int s0 = __ldg(&g_csr_src[e]);
        int s1 = __ldg(&g_csr_src[e + 1]);
        int s2 = __ldg(&g_csr_src[e + 2]);
        int s3 = __ldg(&g_csr_src[e + 3]);
        float4 v0 = __ldg(&h4[(size_t)s0 * 32 + lane]);
        float4 v1 = __ldg(&h4[(size_t)s1 * 32 + lane]);
        float4 v2 = __ldg(&h4[(size_t)s2 * 32 + lane]);
        float4 v3 = __ldg(&h4[(size_t)s3 * 32 + lane]);
        acc.x += v0.x + v1.x + v2.x + v3.x;
        acc.y += v0.y + v1.y + v2.y + v3.y;
        acc.z += v0.z + v1.z + v2.z + v3.z;
        acc.w += v0.w + v1.w + v2.w + v3.w;
    }
    for (; e < end; e++) {
        int s = __ldg(&g_csr_src[e]);
        float4 v = __ldg(&h4[(size_t)s * 32 + lane]);
        acc.x += v.x; acc.y += v.y; acc.z += v.z; acc.w += v.w;
    }
    reinterpret_cast<float4*>(g_agg)[(size_t)node * 32 + lane] = acc;
}

// ---------------- GEMM micro-kernel core (128x128 tile, K=128, f32x2) ----------------
struct AccT { unsigned long long v[8][4]; };

__device__ __forceinline__ void gemm_tile(
    const float* __restrict__ A, const float* __restrict__ W,
    int m0, int tid, float* As, float* Bs, AccT& acc)
{
    int tx = tid & 15;
    int ty = tid >> 4;
    for (int k0 = 0; k0 < 128; k0 += 16) {
        #pragma unroll
        for (int i = 0; i < 2; i++) {
            int f = tid * 2 + i;
            int row = f >> 2;
            int c4 = f & 3;
            int gr = m0 + row;
            float4 v = make_float4(0.f, 0.f, 0.f, 0.f);
            if (gr < N_NODES)
                v = *reinterpret_cast<const float4*>(A + (size_t)gr * 128 + k0 + c4 * 4);
            *reinterpret_cast<float4*>(&As[row * 16 + c4 * 4]) = v;
        }
        #pragma unroll
        for (int i = 0; i < 2; i++) {
            int f = tid * 2 + i;
            int kr = f >> 5;
            int c4 = f & 31;
            float4 v = *reinterpret_cast<const float4*>(W + (size_t)(k0 + kr) * 128 + c4 * 4);
            *reinterpret_cast<float4*>(&Bs[kr * 128 + c4 * 4]) = v;
        }
        __syncthreads();

        #pragma unroll
        for (int k = 0; k < 16; k += 4) {
            float4 av[8];
            #pragma unroll
            for (int r = 0; r < 8; r++)
                av[r] = *reinterpret_cast<const float4*>(&As[(ty * 8 + r) * 16 + k]);
            #pragma unroll
            for (int kk = 0; kk < 4; kk++) {
                unsigned long long bb[4];
                const unsigned long long* Brow =
                    reinterpret_cast<const unsigned long long*>(&Bs[(k + kk) * 128]);
                #pragma unroll
                for (int j = 0; j < 4; j++) bb[j] = Brow[tx + 16 * j];
                #pragma unroll
                for (int r = 0; r < 8; r++) {
                    float a = (kk == 0) ? av[r].x : (kk == 1) ? av[r].y
                            : (kk == 2) ? av[r].z : av[r].w;
                    unsigned long long aa;
                    asm("mov.b64 %0,{%1,%2};" : "=l"(aa) : "f"(a), "f"(a));
                    #pragma unroll
                    for (int j = 0; j < 4; j++)
                        asm("fma.rn.f32x2 %0, %1, %2, %0;"
                            : "+l"(acc.v[r][j]) : "l"(aa), "l"(bb[j]));
                }
            }
        }
        __syncthreads();
    }
}

// ---------------- root GEMM: g_tmp = hin @ Wroot + bias ----------------
__global__ __launch_bounds__(256) void rootgemm_kernel(
    const float* __restrict__ x, int sel_in,
    const float* __restrict__ Wroot, const float* __restrict__ bias)
{
    __shared__ float As[128 * 16];
    __shared__ float Bs[16 * 128];
    const float* hin = pick_in(x, sel_in);
    int m0 = blockIdx.x * 128;
    int tid = threadIdx.x;
    AccT acc;
    #pragma unroll
    for (int r = 0; r < 8; r++)
        #pragma unroll
        for (int j = 0; j < 4; j++) acc.v[r][j] = 0ULL;

    gemm_tile(hin, Wroot, m0, tid, As, Bs, acc);

    int tx = tid & 15;
    int ty = tid >> 4;
    #pragma unroll
    for (int r = 0; r < 8; r++) {
        int gr = m0 + ty * 8 + r;
        if (gr >= N_NODES) break;
        #pragma unroll
        for (int j = 0; j < 4; j++) {
            int p = tx + 16 * j;
            float2 v = *reinterpret_cast<float2*>(&acc.v[r][j]);
            v.x += bias[2 * p];
            v.y += bias[2 * p + 1];
            *reinterpret_cast<float2*>(&g_tmp[(size_t)gr * 128 + 2 * p]) = v;
        }
    }
}

// ---------------- rel GEMM: hout = relu(g_agg @ Wrel + g_tmp) ----------------
__global__ __launch_bounds__(256) void relgemm_kernel(
    int sel_out, const float* __restrict__ Wrel)
{
    __shared__ float As[128 * 16];
    __shared__ float Bs[16 * 128];
    float* hout = pick_out(sel_out);
    int m0 = blockIdx.x * 128;
    int tid = threadIdx.x;
    AccT acc;
    #pragma unroll
    for (int r = 0; r < 8; r++)
        #pragma unroll
        for (int j = 0; j < 4; j++) acc.v[r][j] = 0ULL;

    gemm_tile(g_agg, Wrel, m0, tid, As, Bs, acc);

    int tx = tid & 15;
    int ty = tid >> 4;
    #pragma unroll
    for (int r = 0; r < 8; r++) {
        int gr = m0 + ty * 8 + r;
        if (gr >= N_NODES) break;
        #pragma unroll
        for (int j = 0; j < 4; j++) {
            int p = tx + 16 * j;
            float2 t = *reinterpret_cast<const float2*>(&g_tmp[(size_t)gr * 128 + 2 * p]);
            float2 v = *reinterpret_cast<float2*>(&acc.v[r][j]);
            float lo = fmaxf(v.x + t.x, 0.f);
            float hi = fmaxf(v.y + t.y, 0.f);
            *reinterpret_cast<float2*>(&hout[(size_t)gr * 128 + 2 * p]) = make_float2(lo, hi);
        }
    }
}

// ---------------- pool ----------------
__device__ __forceinline__ int lower_bound_batch(int v) {
    int lo = 0, hi = N_NODES;
    while (lo < hi) {
        int m = (lo + hi) >> 1;
        if (g_batch[m] < v) lo = m + 1; else hi = m;
    }
    return lo;
}

__global__ __launch_bounds__(128) void pool_kernel(const float* __restrict__ x, int sel_in) {
    int g = blockIdx.x;
    int t = threadIdx.x;
    const float* h = pick_in(x, sel_in);
    int lo = lower_bound_batch(g);
    int hi = lower_bound_batch(g + 1);
    float acc = 0.f;
    for (int n = lo; n < hi; n++)
        acc += __ldg(&h[(size_t)n * 128 + t]);
    float cnt = (float)(hi - lo);
    g_pool[(size_t)g * 128 + t] = acc / fmaxf(cnt, 1.0f);
}

// ---------------- fc1 ----------------
__global__ __launch_bounds__(256) void fc1_kernel(
    const float* __restrict__ w, const float* __restrict__ b)
{
    __shared__ float p[4][128];
    int g0 = blockIdx.x * 4;
    int t = threadIdx.x;
    #pragma unroll
    for (int i = 0; i < 2; i++) {
        int f = t + i * 256;
        p[f >> 7][f & 127] = g_pool[(size_t)g0 * 128 + f];
    }
    __syncthreads();
    float acc0 = b[t], acc1 = b[t], acc2 = b[t], acc3 = b[t];
    #pragma unroll 4
    for (int k = 0; k < 128; k++) {
        float wv = __ldg(&w[(size_t)k * 256 + t]);
        acc0 = fmaf(p[0][k], wv, acc0);
        acc1 = fmaf(p[1][k], wv, acc1);
        acc2 = fmaf(p[2][k], wv, acc2);
        acc3 = fmaf(p[3][k], wv, acc3);
    }
    g_fc1[(size_t)(g0 + 0) * 256 + t] = acc0;
    g_fc1[(size_t)(g0 + 1) * 256 + t] = acc1;
    g_fc1[(size_t)(g0 + 2) * 256 + t] = acc2;
    g_fc1[(size_t)(g0 + 3) * 256 + t] = acc3;
}

// ---------------- fc2 ----------------
__global__ void fc2_kernel(const float* __restrict__ w, const float* __restrict__ b,
                           float* __restrict__ out)
{
    int idx = blockIdx.x * blockDim.x + threadIdx.x;
    if (idx >= N_GRAPHS * DOUT) return;
    int g = idx >> 3, o = idx & 7;
    float acc = b[o];
    #pragma unroll 8
    for (int k = 0; k < 256; k++)
        acc = fmaf(g_fc1[(size_t)g * 256 + k], __ldg(&w[k * 8 + o]), acc);
    out[idx] = acc;
}

// ---------------- launch ----------------
extern "C" void kernel_launch(void* const* d_in, const int* in_sizes, int n_in,
                              void* d_out, int out_size)
{
    const float* x = (const float*)d_in[0];
    const void* ei = d_in[1];
    const void* batch = d_in[2];
    const float* Wrel[4]  = {(const float*)d_in[3], (const float*)d_in[6],
                             (const float*)d_in[9], (const float*)d_in[12]};
    const float* Wroot[4] = {(const float*)d_in[4], (const float*)d_in[7],
                             (const float*)d_in[10], (const float*)d_in[13]};
    const float* bias[4]  = {(const float*)d_in[5], (const float*)d_in[8],
                             (const float*)d_in[11], (const float*)d_in[14]};
    const float* fcw = (const float*)d_in[15];
    const float* fcb = (const float*)d_in[16];
    const float* regw = (const float*)d_in[17];
    const float* regb = (const float*)d_in[18];
    float* out = (float*)d_out;

    // one-time side-stream + events (created in the uncaptured correctness call)
    static cudaStream_t s1 = nullptr;
    static cudaEvent_t evF[4], evJ[4];
    if (!s1) {
        cudaStreamCreateWithFlags(&s1, cudaStreamNonBlocking);
        for (int i = 0; i < 4; i++) {
            cudaEventCreateWithFlags(&evF[i], cudaEventDisableTiming);
            cudaEventCreateWithFlags(&evJ[i], cudaEventDisableTiming);
        }
    }

    void* countsPtr = nullptr;
    cudaGetSymbolAddress(&countsPtr, g_counts);
    cudaMemsetAsync(countsPtr, 0, N_NODES * sizeof(int));

    // CSR build (null stream)
    convert_count_kernel<<<(N_EDGES + 255) / 256, 256>>>(ei, batch);
    scan1_kernel<<<SCAN_NB, 256>>>();
    scan2_kernel<<<1, 32>>>();
    scan3_kernel<<<SCAN_NB, 256>>>();
    fill_kernel<<<(N_EDGES + 255) / 256, 256>>>();

    const int gatherBlocks = (int)(((long long)N_NODES * 32 + 255) / 256);
    const int gemmBlocks = (N_NODES + 127) / 128;

    int ins[4]  = {0, 1, 2, 1};
    int outs[4] = {1, 2, 1, 2};
    for (int L = 0; L < 4; L++) {
        // fork: rootGEMM on s1 concurrent with gather on null stream
        cudaEventRecord(evF[L], 0);
        cudaStreamWaitEvent(s1, evF[L], 0);
        rootgemm_kernel<<<gemmBlocks, 256, 0, s1>>>(x, ins[L], Wroot[L], bias[L]);
        cudaEventRecord(evJ[L], s1);

        gather_kernel<<<gatherBlocks, 256>>>(x, ins[L]);

        // join: relGEMM needs both g_agg and g_tmp
        cudaStreamWaitEvent(0, evJ[L], 0);
        relgemm_kernel<<<gemmBlocks, 256>>>(outs[L], Wrel[L]);
    }

    pool_kernel<<<N_GRAPHS, 128>>>(x, 2);
    fc1_kernel<<<N_GRAPHS / 4, 256>>>(fcw, fcb);
    fc2_kernel<<<(N_GRAPHS * DOUT + 127) / 128, 128>>>(regw, regb, out);
}

// round 6
// speedup vs baseline: 2.3994x; 1.4445x over previous
#include <cuda_runtime.h>
#include <cstdint>

#define N_NODES 100000
#define N_EDGES 1600000
#define N_GRAPHS 2048
#define D 128
#define DFC 256
#define DOUT 8

#define SCAN_CHUNK 1024
#define SCAN_NB ((N_NODES + SCAN_CHUNK - 1) / SCAN_CHUNK)   // 98

// ---------------- scratch (static device globals; no allocation) ----------------
__device__ float g_agg[(size_t)N_NODES * D];
__device__ float g_hA[(size_t)N_NODES * D];
__device__ float g_hB[(size_t)N_NODES * D];
__device__ float g_pool[(size_t)N_GRAPHS * D];
__device__ float g_fc1[(size_t)N_GRAPHS * DFC];
__device__ int   g_src[N_EDGES];
__device__ int   g_dst[N_EDGES];
__device__ int   g_batch[N_NODES];
__device__ int   g_counts[N_NODES];          // zeroed by cudaMemsetAsync
__device__ int   g_row_ptr[N_NODES + 1];
__device__ int   g_cursor[N_NODES];
__device__ int   g_csr_src[N_EDGES];
__device__ int   g_blocksum[SCAN_NB];

// selector: 0 -> external x, 1 -> g_hA, 2 -> g_hB
__device__ __forceinline__ const float* pick_in(const float* x, int sel) {
    return sel == 0 ? x : (sel == 1 ? g_hA : g_hB);
}
__device__ __forceinline__ float* pick_out(int sel) {
    return sel == 1 ? g_hA : g_hB;
}

// ---------------- convert indices (self-detecting dtype) + per-dst counts ----------------
__device__ __forceinline__ int detect_is64(const void* ei) {
    const long long* p64 = (const long long*)ei;
    int ok = 1;
    #pragma unroll
    for (int i = 0; i < 16; i++) {
        long long v = __ldg(&p64[i]);
        if (v < 0 || v >= N_NODES) ok = 0;
    }
    return ok;
}

__global__ void convert_count_kernel(const void* ei, const void* batch) {
    int i = blockIdx.x * blockDim.x + threadIdx.x;
    int is64 = detect_is64(ei);
    if (i < N_EDGES) {
        int s, d;
        if (is64) {
            const long long* p = (const long long*)ei;
            s = (int)__ldg(&p[i]);
            d = (int)__ldg(&p[(size_t)N_EDGES + i]);
        } else {
            const int* p = (const int*)ei;
            s = __ldg(&p[i]);
            d = __ldg(&p[N_EDGES + i]);
        }
        g_src[i] = s;
        g_dst[i] = d;
        atomicAdd(&g_counts[d], 1);
    }
    if (i < N_NODES) {
        if (is64) g_batch[i] = (int)__ldg(&((const long long*)batch)[i]);
        else      g_batch[i] = __ldg(&((const int*)batch)[i]);
    }
}

// ---------------- scan: counts -> row_ptr (exclusive) ----------------
__global__ void scan1_kernel() {
    __shared__ int sh[256];
    int b = blockIdx.x, t = threadIdx.x;
    int i0 = b * SCAN_CHUNK + t * 4;
    int s = 0;
    #pragma unroll
    for (int j = 0; j < 4; j++) {
        int i = i0 + j;
        if (i < N_NODES) s += g_counts[i];
    }
    sh[t] = s;
    __syncthreads();
    for (int off = 128; off > 0; off >>= 1) {
        if (t < off) sh[t] += sh[t + off];
        __syncthreads();
    }
    if (t == 0) g_blocksum[b] = sh[0];
}

// parallel exclusive scan of the 98 chunk totals (one block)
__global__ void scan2_kernel() {
    __shared__ int sh[128];
    int t = threadIdx.x;
    int v = (t < SCAN_NB) ? g_blocksum[t] : 0;
    sh[t] = v;
    __syncthreads();
    #pragma unroll
    for (int off = 1; off < 128; off <<= 1) {
        int u = (t >= off) ? sh[t - off] : 0;
        __syncthreads();
        sh[t] += u;
        __syncthreads();
    }
    if (t < SCAN_NB) g_blocksum[t] = sh[t] - v;   // exclusive
    if (t == 127) g_row_ptr[N_NODES] = sh[127];
}

__global__ void scan3_kernel() {
    __shared__ int sh[256];
    int b = blockIdx.x, t = threadIdx.x;
    int i0 = b * SCAN_CHUNK + t * 4;
    int c[4];
    int tsum = 0;
    #pragma unroll
    for (int j = 0; j < 4; j++) {
        int i = i0 + j;
        c[j] = (i < N_NODES) ? g_counts[i] : 0;
        tsum += c[j];
    }
    sh[t] = tsum;
    __syncthreads();
    #pragma unroll
    for (int off = 1; off < 256; off <<= 1) {
        int v = (t >= off) ? sh[t - off] : 0;
        __syncthreads();
        sh[t] += v;
        __syncthreads();
    }
    int base = g_blocksum[b] + sh[t] - tsum;
    #pragma unroll
    for (int j = 0; j < 4; j++) {
        int i = i0 + j;
        if (i < N_NODES) {
            g_row_ptr[i] = base;
            g_cursor[i]  = base;
            base += c[j];
        }
    }
}

// ---------------- fill CSR ----------------
__global__ void fill_kernel() {
    int e = blockIdx.x * blockDim.x + threadIdx.x;
    if (e >= N_EDGES) return;
    int d = g_dst[e];
    int pos = atomicAdd(&g_cursor[d], 1);
    g_csr_src[pos] = g_src[e];
}

// ---------------- gather: agg[n] = sum over csr edges of h[src] (R2-proven) ----------------
__global__ void gather_kernel(const float* __restrict__ x, int sel_in) {
    long long idx = (long long)blockIdx.x * blockDim.x + threadIdx.x;
    int node = (int)(idx >> 5);
    if (node >= N_NODES) return;
    int lane = (int)(idx & 31);
    const float* h = pick_in(x, sel_in);
    const float4* h4 = reinterpret_cast<const float4*>(h);
    int beg = g_row_ptr[node];
    int end = g_row_ptr[node + 1];
    float4 acc = make_float4(0.f, 0.f, 0.f, 0.f);
    int e = beg;
    for (; e + 4 <= end; e += 4) {
        int s0 = __ldg(&g_csr_src[e]);
        int s1 = __ldg(&g_csr_src[e + 1]);
        int s2 = __ldg(&g_csr_src[e + 2]);
        int s3 = __ldg(&g_csr_src[e + 3]);
        float4 v0 = __ldg(&h4[(size_t)s0 * 32 + lane]);
        float4 v1 = __ldg(&h4[(size_t)s1 * 32 + lane]);
        float4 v2 = __ldg(&h4[(size_t)s2 * 32 + lane]);
        float4 v3 = __ldg(&h4[(size_t)s3 * 32 + lane]);
        acc.x += v0.x + v1.x + v2.x + v3.x;
        acc.y += v0.y + v1.y + v2.y + v3.y;
        acc.z += v0.z + v1.z + v2.z + v3.z;
        acc.w += v0.w + v1.w + v2.w + v3.w;
    }
    for (; e < end; e++) {
        int s = __ldg(&g_csr_src[e]);
        float4 v = __ldg(&h4[(size_t)s * 32 + lane]);
        acc.x += v.x; acc.y += v.y; acc.z += v.z; acc.w += v.w;
    }
    reinterpret_cast<float4*>(g_agg)[(size_t)node * 32 + lane] = acc;
}

// ---------------- fused dual-GEMM + bias + relu, single-pass staging -------------
// out = relu(agg @ Wrel + hin @ Wroot + b)
// Per k-chunk (16 wide) stage ALL FOUR tiles, one barrier pair, both FMA chains
// into the same accumulator: 8 chunks x 2 syncs = 16 barriers (was 64).
__global__ __launch_bounds__(256) void gemm_fused_kernel(
    const float* __restrict__ x, int sel_in, int sel_out,
    const float* __restrict__ Wrel, const float* __restrict__ Wroot,
    const float* __restrict__ bias)
{
    __shared__ float Aa[128 * 16];   // agg chunk
    __shared__ float Ah[128 * 16];   // hin chunk
    __shared__ float Br[16 * 128];   // Wrel chunk
    __shared__ float Bo[16 * 128];   // Wroot chunk

    const float* hin = pick_in(x, sel_in);
    float* hout = pick_out(sel_out);

    int m0 = blockIdx.x * 128;
    int tid = threadIdx.x;
    int tx = tid & 15;
    int ty = tid >> 4;

    unsigned long long acc[8][4];
    #pragma unroll
    for (int r = 0; r < 8; r++)
        #pragma unroll
        for (int j = 0; j < 4; j++) acc[r][j] = 0ULL;

    for (int k0 = 0; k0 < 128; k0 += 16) {
        // stage A tiles (agg + hin): 512 float4 each, 2 per thread
        #pragma unroll
        for (int i = 0; i < 2; i++) {
            int f = tid * 2 + i;
            int row = f >> 2;
            int c4 = f & 3;
            int gr = m0 + row;
            float4 va = make_float4(0.f, 0.f, 0.f, 0.f);
            float4 vh = make_float4(0.f, 0.f, 0.f, 0.f);
            if (gr < N_NODES) {
                va = *reinterpret_cast<const float4*>(g_agg + (size_t)gr * 128 + k0 + c4 * 4);
                vh = *reinterpret_cast<const float4*>(hin   + (size_t)gr * 128 + k0 + c4 * 4);
            }
            *reinterpret_cast<float4*>(&Aa[row * 16 + c4 * 4]) = va;
            *reinterpret_cast<float4*>(&Ah[row * 16 + c4 * 4]) = vh;
        }
        // stage W tiles (rel + root): 512 float4 each
        #pragma unroll
        for (int i = 0; i < 2; i++) {
            int f = tid * 2 + i;
            int kr = f >> 5;
            int c4 = f & 31;
            float4 vr = *reinterpret_cast<const float4*>(Wrel  + (size_t)(k0 + kr) * 128 + c4 * 4);
            float4 vo = *reinterpret_cast<const float4*>(Wroot + (size_t)(k0 + kr) * 128 + c4 * 4);
            *reinterpret_cast<float4*>(&Br[kr * 128 + c4 * 4]) = vr;
            *reinterpret_cast<float4*>(&Bo[kr * 128 + c4 * 4]) = vo;
        }
        __syncthreads();

        #pragma unroll
        for (int k = 0; k < 16; k += 4) {
            // ---- agg @ Wrel ----
            {
                float4 av[8];
                #pragma unroll
                for (int r = 0; r < 8; r++)
                    av[r] = *reinterpret_cast<const float4*>(&Aa[(ty * 8 + r) * 16 + k]);
                #pragma unroll
                for (int kk = 0; kk < 4; kk++) {
                    unsigned long long bb[4];
                    const unsigned long long* Brow =
                        reinterpret_cast<const unsigned long long*>(&Br[(k + kk) * 128]);
                    #pragma unroll
                    for (int j = 0; j < 4; j++) bb[j] = Brow[tx + 16 * j];
                    #pragma unroll
                    for (int r = 0; r < 8; r++) {
                        float a = (kk == 0) ? av[r].x : (kk == 1) ? av[r].y
                                : (kk == 2) ? av[r].z : av[r].w;
                        unsigned long long aa;
                        asm("mov.b64 %0,{%1,%2};" : "=l"(aa) : "f"(a), "f"(a));
                        #pragma unroll
                        for (int j = 0; j < 4; j++)
                            asm("fma.rn.f32x2 %0, %1, %2, %0;"
                                : "+l"(acc[r][j]) : "l"(aa), "l"(bb[j]));
                    }
                }
            }
            // ---- hin @ Wroot ----
            {
                float4 av[8];
                #pragma unroll
                for (int r = 0; r < 8; r++)
                    av[r] = *reinterpret_cast<const float4*>(&Ah[(ty * 8 + r) * 16 + k]);
                #pragma unroll
                for (int kk = 0; kk < 4; kk++) {
                    unsigned long long bb[4];
                    const unsigned long long* Brow =
                        reinterpret_cast<const unsigned long long*>(&Bo[(k + kk) * 128]);
                    #pragma unroll
                    for (int j = 0; j < 4; j++) bb[j] = Brow[tx + 16 * j];
                    #pragma unroll
                    for (int r = 0; r < 8; r++) {
                        float a = (kk == 0) ? av[r].x : (kk == 1) ? av[r].y
                                : (kk == 2) ? av[r].z : av[r].w;
                        unsigned long long aa;
                        asm("mov.b64 %0,{%1,%2};" : "=l"(aa) : "f"(a), "f"(a));
                        #pragma unroll
                        for (int j = 0; j < 4; j++)
                            asm("fma.rn.f32x2 %0, %1, %2, %0;"
                                : "+l"(acc[r][j]) : "l"(aa), "l"(bb[j]));
                    }
                }
            }
        }
        __syncthreads();
    }

    // epilogue: bias + relu + store
    #pragma unroll
    for (int r = 0; r < 8; r++) {
        int gr = m0 + ty * 8 + r;
        if (gr >= N_NODES) break;
        #pragma unroll
        for (int j = 0; j < 4; j++) {
            int p = tx + 16 * j;
            float2 v = *reinterpret_cast<float2*>(&acc[r][j]);
            float lo = fmaxf(v.x + bias[2 * p], 0.f);
            float hi = fmaxf(v.y + bias[2 * p + 1], 0.f);
            *reinterpret_cast<float2*>(&hout[(size_t)gr * 128 + 2 * p]) = make_float2(lo, hi);
        }
    }
}

// ---------------- pool: sorted-batch segments, block per graph, no atomics ----------------
__device__ __forceinline__ int lower_bound_batch(int v) {
    int lo = 0, hi = N_NODES;
    while (lo < hi) {
        int m = (lo + hi) >> 1;
        if (g_batch[m] < v) lo = m + 1; else hi = m;
    }
    return lo;
}

__global__ __launch_bounds__(128) void pool_kernel(const float* __restrict__ x, int sel_in) {
    int g = blockIdx.x;
    int t = threadIdx.x;
    const float* h = pick_in(x, sel_in);
    int lo = lower_bound_batch(g);
    int hi = lower_bound_batch(g + 1);
    float acc = 0.f;
    for (int n = lo; n < hi; n++)
        acc += __ldg(&h[(size_t)n * 128 + t]);
    float cnt = (float)(hi - lo);
    g_pool[(size_t)g * 128 + t] = acc / fmaxf(cnt, 1.0f);
}

// ---------------- fc1: 4 graphs per block ----------------
__global__ __launch_bounds__(256) void fc1_kernel(
    const float* __restrict__ w, const float* __restrict__ b)
{
    __shared__ float p[4][128];
    int g0 = blockIdx.x * 4;
    int t = threadIdx.x;
    #pragma unroll
    for (int i = 0; i < 2; i++) {
        int f = t + i * 256;
        p[f >> 7][f & 127] = g_pool[(size_t)g0 * 128 + f];
    }
    __syncthreads();
    float acc0 = b[t], acc1 = b[t], acc2 = b[t], acc3 = b[t];
    #pragma unroll 4
    for (int k = 0; k < 128; k++) {
        float wv = __ldg(&w[(size_t)k * 256 + t]);
        acc0 = fmaf(p[0][k], wv, acc0);
        acc1 = fmaf(p[1][k], wv, acc1);
        acc2 = fmaf(p[2][k], wv, acc2);
        acc3 = fmaf(p[3][k], wv, acc3);
    }
    g_fc1[(size_t)(g0 + 0) * 256 + t] = acc0;
    g_fc1[(size_t)(g0 + 1) * 256 + t] = acc1;
    g_fc1[(size_t)(g0 + 2) * 256 + t] = acc2;
    g_fc1[(size_t)(g0 + 3) * 256 + t] = acc3;
}

// ---------------- fc2 ----------------
__global__ void fc2_kernel(const float* __restrict__ w, const float* __restrict__ b,
                           float* __restrict__ out)
{
    int idx = blockIdx.x * blockDim.x + threadIdx.x;
    if (idx >= N_GRAPHS * DOUT) return;
    int g = idx >> 3, o = idx & 7;
    float acc = b[o];
    #pragma unroll 8
    for (int k = 0; k < 256; k++)
        acc = fmaf(g_fc1[(size_t)g * 256 + k], __ldg(&w[k * 8 + o]), acc);
    out[idx] = acc;
}

// ---------------- launch ----------------
extern "C" void kernel_launch(void* const* d_in, const int* in_sizes, int n_in,
                              void* d_out, int out_size)
{
    const float* x = (const float*)d_in[0];
    const void* ei = d_in[1];
    const void* batch = d_in[2];
    const float* Wrel[4]  = {(const float*)d_in[3], (const float*)d_in[6],
                             (const float*)d_in[9], (const float*)d_in[12]};
    const float* Wroot[4] = {(const float*)d_in[4], (const float*)d_in[7],
                             (const float*)d_in[10], (const float*)d_in[13]};
    const float* bias[4]  = {(const float*)d_in[5], (const float*)d_in[8],
                             (const float*)d_in[11], (const float*)d_in[14]};
    const float* fcw = (const float*)d_in[15];
    const float* fcb = (const float*)d_in[16];
    const float* regw = (const float*)d_in[17];
    const float* regb = (const float*)d_in[18];
    float* out = (float*)d_out;

    void* countsPtr = nullptr;
    cudaGetSymbolAddress(&countsPtr, g_counts);
    cudaMemsetAsync(countsPtr, 0, N_NODES * sizeof(int));

    // CSR build
    convert_count_kernel<<<(N_EDGES + 255) / 256, 256>>>(ei, batch);
    scan1_kernel<<<SCAN_NB, 256>>>();
    scan2_kernel<<<1, 128>>>();
    scan3_kernel<<<SCAN_NB, 256>>>();
    fill_kernel<<<(N_EDGES + 255) / 256, 256>>>();

    const int gatherBlocks = (int)(((long long)N_NODES * 32 + 255) / 256);
    const int gemmBlocks = (N_NODES + 127) / 128;

    int ins[4]  = {0, 1, 2, 1};
    int outs[4] = {1, 2, 1, 2};
    for (int L = 0; L < 4; L++) {
        gather_kernel<<<gatherBlocks, 256>>>(x, ins[L]);
        gemm_fused_kernel<<<gemmBlocks, 256>>>(x, ins[L], outs[L],
                                               Wrel[L], Wroot[L], bias[L]);
    }

    pool_kernel<<<N_GRAPHS, 128>>>(x, 2);
    fc1_kernel<<<N_GRAPHS / 4, 256>>>(fcw, fcb);
    fc2_kernel<<<(N_GRAPHS * DOUT + 127) / 128, 128>>>(regw, regb, out);
}

// round 9
// speedup vs baseline: 4.1441x; 1.7272x over previous
#include <cuda_runtime.h>
#include <cstdint>

#define N_NODES 100000
#define N_EDGES 1600000
#define N_GRAPHS 2048
#define D 128
#define DFC 256
#define DOUT 8

#define SCAN_CHUNK 1024
#define SCAN_NB ((N_NODES + SCAN_CHUNK - 1) / SCAN_CHUNK)   // 98

#define SA 20     // A smem stride (floats): banks (20g+t)%32 all distinct
#define SB 136    // B smem stride (floats): banks (8t+g)%32 all distinct

// ---------------- scratch (static device globals; no allocation) ----------------
__device__ float g_agg[(size_t)N_NODES * D];
__device__ float g_hA[(size_t)N_NODES * D];
__device__ float g_hB[(size_t)N_NODES * D];
__device__ float g_pool[(size_t)N_GRAPHS * D];
__device__ float g_fc1[(size_t)N_GRAPHS * DFC];
__device__ int   g_src[N_EDGES];
__device__ int   g_dst[N_EDGES];
__device__ int   g_batch[N_NODES];
__device__ int   g_counts[N_NODES];          // zeroed by cudaMemsetAsync
__device__ int   g_row_ptr[N_NODES + 1];
__device__ int   g_cursor[N_NODES];
__device__ int   g_csr_src[N_EDGES];
__device__ int   g_blocksum[SCAN_NB];

__device__ __forceinline__ const float* pick_in(const float* x, int sel) {
    return sel == 0 ? x : (sel == 1 ? g_hA : g_hB);
}
__device__ __forceinline__ float* pick_out(int sel) {
    return sel == 1 ? g_hA : g_hB;
}

// ---------------- tf32 helpers ----------------
__device__ __forceinline__ uint32_t f2tf32(float v) {
    uint32_t r;
    asm("cvt.rna.tf32.f32 %0, %1;" : "=r"(r) : "f"(v));
    return r;
}

__device__ __forceinline__ void mma_tf32(float* c, const uint32_t* a,
                                         uint32_t b0, uint32_t b1) {
    asm("mma.sync.aligned.m16n8k8.row.col.f32.tf32.tf32.f32 "
        "{%0,%1,%2,%3},{%4,%5,%6,%7},{%8,%9},{%0,%1,%2,%3};"
        : "+f"(c[0]), "+f"(c[1]), "+f"(c[2]), "+f"(c[3])
        : "r"(a[0]), "r"(a[1]), "r"(a[2]), "r"(a[3]), "r"(b0), "r"(b1));
}

// ---------------- convert indices (self-detecting dtype) + per-dst counts ----------------
__device__ __forceinline__ int detect_is64(const void* ei) {
    const long long* p64 = (const long long*)ei;
    int ok = 1;
    #pragma unroll
    for (int i = 0; i < 16; i++) {
        long long v = __ldg(&p64[i]);
        if (v < 0 || v >= N_NODES) ok = 0;
    }
    return ok;
}

__global__ void convert_count_kernel(const void* ei, const void* batch) {
    int i = blockIdx.x * blockDim.x + threadIdx.x;
    int is64 = detect_is64(ei);
    if (i < N_EDGES) {
        int s, d;
        if (is64) {
            const long long* p = (const long long*)ei;
            s = (int)__ldg(&p[i]);
            d = (int)__ldg(&p[(size_t)N_EDGES + i]);
        } else {
            const int* p = (const int*)ei;
            s = __ldg(&p[i]);
            d = __ldg(&p[N_EDGES + i]);
        }
        g_src[i] = s;
        g_dst[i] = d;
        atomicAdd(&g_counts[d], 1);
    }
    if (i < N_NODES) {
        if (is64) g_batch[i] = (int)__ldg(&((const long long*)batch)[i]);
        else      g_batch[i] = __ldg(&((const int*)batch)[i]);
    }
}

// ---------------- scan: counts -> row_ptr (exclusive) ----------------
__global__ void scan1_kernel() {
    __shared__ int sh[256];
    int b = blockIdx.x, t = threadIdx.x;
    int i0 = b * SCAN_CHUNK + t * 4;
    int s = 0;
    #pragma unroll
    for (int j = 0; j < 4; j++) {
        int i = i0 + j;
        if (i < N_NODES) s += g_counts[i];
    }
    sh[t] = s;
    __syncthreads();
    for (int off = 128; off > 0; off >>= 1) {
        if (t < off) sh[t] += sh[t + off];
        __syncthreads();
    }
    if (t == 0) g_blocksum[b] = sh[0];
}

__global__ void scan2_kernel() {
    __shared__ int sh[128];
    int t = threadIdx.x;
    int v = (t < SCAN_NB) ? g_blocksum[t] : 0;
    sh[t] = v;
    __syncthreads();
    #pragma unroll
    for (int off = 1; off < 128; off <<= 1) {
        int u = (t >= off) ? sh[t - off] : 0;
        __syncthreads();
        sh[t] += u;
        __syncthreads();
    }
    if (t < SCAN_NB) g_blocksum[t] = sh[t] - v;   // exclusive
    if (t == 127) g_row_ptr[N_NODES] = sh[127];
}

__global__ void scan3_kernel() {
    __shared__ int sh[256];
    int b = blockIdx.x, t = threadIdx.x;
    int i0 = b * SCAN_CHUNK + t * 4;
    int c[4];
    int tsum = 0;
    #pragma unroll
    for (int j = 0; j < 4; j++) {
        int i = i0 + j;
        c[j] = (i < N_NODES) ? g_counts[i] : 0;
        tsum += c[j];
    }
    sh[t] = tsum;
    __syncthreads();
    #pragma unroll
    for (int off = 1; off < 256; off <<= 1) {
        int v = (t >= off) ? sh[t - off] : 0;
        __syncthreads();
        sh[t] += v;
        __syncthreads();
    }
    int base = g_blocksum[b] + sh[t] - tsum;
    #pragma unroll
    for (int j = 0; j < 4; j++) {
        int i = i0 + j;
        if (i < N_NODES) {
            g_row_ptr[i] = base;
            g_cursor[i]  = base;
            base += c[j];
        }
    }
}

// ---------------- fill CSR ----------------
__global__ void fill_kernel() {
    int e = blockIdx.x * blockDim.x + threadIdx.x;
    if (e >= N_EDGES) return;
    int d = g_dst[e];
    int pos = atomicAdd(&g_cursor[d], 1);
    g_csr_src[pos] = g_src[e];
}

// ---------------- gather: agg[n] = sum over csr edges of h[src] (R2-proven) ----------------
__global__ void gather_kernel(const float* __restrict__ x, int sel_in) {
    long long idx = (long long)blockIdx.x * blockDim.x + threadIdx.x;
    int node = (int)(idx >> 5);
    if (node >= N_NODES) return;
    int lane = (int)(idx & 31);
    const float* h = pick_in(x, sel_in);
    const float4* h4 = reinterpret_cast<const float4*>(h);
    int beg = g_row_ptr[node];
    int end = g_row_ptr[node + 1];
    float4 acc = make_float4(0.f, 0.f, 0.f, 0.f);
    int e = beg;
    for (; e + 4 <= end; e += 4) {
        int s0 = __ldg(&g_csr_src[e]);
        int s1 = __ldg(&g_csr_src[e + 1]);
        int s2 = __ldg(&g_csr_src[e + 2]);
        int s3 = __ldg(&g_csr_src[e + 3]);
        float4 v0 = __ldg(&h4[(size_t)s0 * 32 + lane]);
        float4 v1 = __ldg(&h4[(size_t)s1 * 32 + lane]);
        float4 v2 = __ldg(&h4[(size_t)s2 * 32 + lane]);
        float4 v3 = __ldg(&h4[(size_t)s3 * 32 + lane]);
        acc.x += v0.x + v1.x + v2.x + v3.x;
        acc.y += v0.y + v1.y + v2.y + v3.y;
        acc.z += v0.z + v1.z + v2.z + v3.z;
        acc.w += v0.w + v1.w + v2.w + v3.w;
    }
    for (; e < end; e++) {
        int s = __ldg(&g_csr_src[e]);
        float4 v = __ldg(&h4[(size_t)s * 32 + lane]);
        acc.x += v.x; acc.y += v.y; acc.z += v.z; acc.w += v.w;
    }
    reinterpret_cast<float4*>(g_agg)[(size_t)node * 32 + lane] = acc;
}

// ---------------- fused dual-GEMM via tf32 mma.sync ----------------
// out = relu(agg @ Wrel + hin @ Wroot + b), fp32 accumulate.
// 8 warps: warp_m (0..3) x warp_n (0..1); warp tile 32x64 = 2 m-frags x 8 n-frags.
__device__ __forceinline__ void mma_pair(
    const uint32_t* __restrict__ As_, const uint32_t* __restrict__ Bs_,
    int kc, int warp_m, int warp_n, int g, int t, float acc[2][8][4])
{
    uint32_t afr[2][4];
    #pragma unroll
    for (int mt = 0; mt < 2; mt++) {
        int r0 = warp_m * 32 + mt * 16;
        afr[mt][0] = As_[(r0 + g) * SA + kc + t];
        afr[mt][1] = As_[(r0 + g + 8) * SA + kc + t];
        afr[mt][2] = As_[(r0 + g) * SA + kc + t + 4];
        afr[mt][3] = As_[(r0 + g + 8) * SA + kc + t + 4];
    }
    #pragma unroll
    for (int nt = 0; nt < 8; nt++) {
        int n0 = warp_n * 64 + nt * 8;
        uint32_t b0 = Bs_[(kc + t) * SB + n0 + g];
        uint32_t b1 = Bs_[(kc + t + 4) * SB + n0 + g];
        mma_tf32(acc[0][nt], afr[0], b0, b1);
        mma_tf32(acc[1][nt], afr[1], b0, b1);
    }
}

__global__ __launch_bounds__(256) void gemm_fused_kernel(
    const float* __restrict__ x, int sel_in, int sel_out,
    const float* __restrict__ Wrel, const float* __restrict__ Wroot,
    const float* __restrict__ bias)
{
    __shared__ uint32_t Aa[128 * SA];
    __shared__ uint32_t Ah[128 * SA];
    __shared__ uint32_t Br[16 * SB];
    __shared__ uint32_t Bo[16 * SB];

    const float* hin = pick_in(x, sel_in);
    float* hout = pick_out(sel_out);

    int m0 = blockIdx.x * 128;
    int tid = threadIdx.x;
    int wid = tid >> 5;
    int lane = tid & 31;
    int warp_m = wid & 3;
    int warp_n = wid >> 2;
    int g = lane >> 2;
    int t = lane & 3;

    float acc[2][8][4];
    #pragma unroll
    for (int mt = 0; mt < 2; mt++)
        #pragma unroll
        for (int nt = 0; nt < 8; nt++)
            #pragma unroll
            for (int j = 0; j < 4; j++) acc[mt][nt][j] = 0.f;

    for (int k0 = 0; k0 < 128; k0 += 16) {
        // stage A tiles (agg + hin), converted to tf32
        #pragma unroll
        for (int i = 0; i < 2; i++) {
            int f = tid * 2 + i;
            int row = f >> 2;
            int c4 = f & 3;
            int gr = m0 + row;
            float4 va = make_float4(0.f, 0.f, 0.f, 0.f);
            float4 vh = make_float4(0.f, 0.f, 0.f, 0.f);
            if (gr < N_NODES) {
                va = *reinterpret_cast<const float4*>(g_agg + (size_t)gr * 128 + k0 + c4 * 4);
                vh = *reinterpret_cast<const float4*>(hin   + (size_t)gr * 128 + k0 + c4 * 4);
            }
            int base = row * SA + c4 * 4;
            Aa[base + 0] = f2tf32(va.x); Aa[base + 1] = f2tf32(va.y);
            Aa[base + 2] = f2tf32(va.z); Aa[base + 3] = f2tf32(va.w);
            Ah[base + 0] = f2tf32(vh.x); Ah[base + 1] = f2tf32(vh.y);
            Ah[base + 2] = f2tf32(vh.z); Ah[base + 3] = f2tf32(vh.w);
        }
        // stage W tiles (rel + root), converted to tf32
        #pragma unroll
        for (int i = 0; i < 2; i++) {
            int f = tid * 2 + i;
            int kr = f >> 5;
            int c4 = f & 31;
            float4 vr = *reinterpret_cast<const float4*>(Wrel  + (size_t)(k0 + kr) * 128 + c4 * 4);
            float4 vo = *reinterpret_cast<const float4*>(Wroot + (size_t)(k0 + kr) * 128 + c4 * 4);
            int base = kr * SB + c4 * 4;
            Br[base + 0] = f2tf32(vr.x); Br[base + 1] = f2tf32(vr.y);
            Br[base + 2] = f2tf32(vr.z); Br[base + 3] = f2tf32(vr.w);
            Bo[base + 0] = f2tf32(vo.x); Bo[base + 1] = f2tf32(vo.y);
            Bo[base + 2] = f2tf32(vo.z); Bo[base + 3] = f2tf32(vo.w);
        }
        __syncthreads();

        #pragma unroll
        for (int kc = 0; kc < 16; kc += 8) {
            mma_pair(Aa, Br, kc, warp_m, warp_n, g, t, acc);
            mma_pair(Ah, Bo, kc, warp_m, warp_n, g, t, acc);
        }
        __syncthreads();
    }

    // epilogue: bias + relu + store (float2 per c-pair)
    #pragma unroll
    for (int nt = 0; nt < 8; nt++) {
        int col = warp_n * 64 + nt * 8 + 2 * t;
        float b0 = __ldg(&bias[col]);
        float b1 = __ldg(&bias[col + 1]);
        #pragma unroll
        for (int mt = 0; mt < 2; mt++) {
            int row0 = m0 + warp_m * 32 + mt * 16 + g;
            if (row0 < N_NODES) {
                float lo = fmaxf(acc[mt][nt][0] + b0, 0.f);
                float hi = fmaxf(acc[mt][nt][1] + b1, 0.f);
                *reinterpret_cast<float2*>(&hout[(size_t)row0 * 128 + col]) =
                    make_float2(lo, hi);
            }
            int row1 = row0 + 8;
            if (row1 < N_NODES) {
                float lo = fmaxf(acc[mt][nt][2] + b0, 0.f);
                float hi = fmaxf(acc[mt][nt][3] + b1, 0.f);
                *reinterpret_cast<float2*>(&hout[(size_t)row1 * 128 + col]) =
                    make_float2(lo, hi);
            }
        }
    }
}

// ---------------- pool: sorted-batch segments, block per graph, no atomics ----------------
__device__ __forceinline__ int lower_bound_batch(int v) {
    int lo = 0, hi = N_NODES;
    while (lo < hi) {
        int m = (lo + hi) >> 1;
        if (g_batch[m] < v) lo = m + 1; else hi = m;
    }
    return lo;
}

__global__ __launch_bounds__(128) void pool_kernel(const float* __restrict__ x, int sel_in) {
    int g = blockIdx.x;
    int t = threadIdx.x;
    const float* h = pick_in(x, sel_in);
    int lo = lower_bound_batch(g);
    int hi = lower_bound_batch(g + 1);
    float acc = 0.f;
    for (int n = lo; n < hi; n++)
        acc += __ldg(&h[(size_t)n * 128 + t]);
    float cnt = (float)(hi - lo);
    g_pool[(size_t)g * 128 + t] = acc / fmaxf(cnt, 1.0f);
}

// ---------------- fc1: 4 graphs per block ----------------
__global__ __launch_bounds__(256) void fc1_kernel(
    const float* __restrict__ w, const float* __restrict__ b)
{
    __shared__ float p[4][128];
    int g0 = blockIdx.x * 4;
    int t = threadIdx.x;
    #pragma unroll
    for (int i = 0; i < 2; i++) {
        int f = t + i * 256;
        p[f >> 7][f & 127] = g_pool[(size_t)g0 * 128 + f];
    }
    __syncthreads();
    float acc0 = b[t], acc1 = b[t], acc2 = b[t], acc3 = b[t];
    #pragma unroll 4
    for (int k = 0; k < 128; k++) {
        float wv = __ldg(&w[(size_t)k * 256 + t]);
        acc0 = fmaf(p[0][k], wv, acc0);
        acc1 = fmaf(p[1][k], wv, acc1);
        acc2 = fmaf(p[2][k], wv, acc2);
        acc3 = fmaf(p[3][k], wv, acc3);
    }
    g_fc1[(size_t)(g0 + 0) * 256 + t] = acc0;
    g_fc1[(size_t)(g0 + 1) * 256 + t] = acc1;
    g_fc1[(size_t)(g0 + 2) * 256 + t] = acc2;
    g_fc1[(size_t)(g0 + 3) * 256 + t] = acc3;
}

// ---------------- fc2 ----------------
__global__ void fc2_kernel(const float* __restrict__ w, const float* __restrict__ b,
                           float* __restrict__ out)
{
    int idx = blockIdx.x * blockDim.x + threadIdx.x;
    if (idx >= N_GRAPHS * DOUT) return;
    int g = idx >> 3, o = idx & 7;
    float acc = b[o];
    #pragma unroll 8
    for (int k = 0; k < 256; k++)
        acc = fmaf(g_fc1[(size_t)g * 256 + k], __ldg(&w[k * 8 + o]), acc);
    out[idx] = acc;
}

// ---------------- launch ----------------
extern "C" void kernel_launch(void* const* d_in, const int* in_sizes, int n_in,
                              void* d_out, int out_size)
{
    const float* x = (const float*)d_in[0];
    const void* ei = d_in[1];
    const void* batch = d_in[2];
    const float* Wrel[4]  = {(const float*)d_in[3], (const float*)d_in[6],
                             (const float*)d_in[9], (const float*)d_in[12]};
    const float* Wroot[4] = {(const float*)d_in[4], (const float*)d_in[7],
                             (const float*)d_in[10], (const float*)d_in[13]};
    const float* bias[4]  = {(const float*)d_in[5], (const float*)d_in[8],
                             (const float*)d_in[11], (const float*)d_in[14]};
    const float* fcw = (const float*)d_in[15];
    const float* fcb = (const float*)d_in[16];
    const float* regw = (const float*)d_in[17];
    const float* regb = (const float*)d_in[18];
    float* out = (float*)d_out;

    void* countsPtr = nullptr;
    cudaGetSymbolAddress(&countsPtr, g_counts);
    cudaMemsetAsync(countsPtr, 0, N_NODES * sizeof(int));

    // CSR build
    convert_count_kernel<<<(N_EDGES + 255) / 256, 256>>>(ei, batch);
    scan1_kernel<<<SCAN_NB, 256>>>();
    scan2_kernel<<<1, 128>>>();
    scan3_kernel<<<SCAN_NB, 256>>>();
    fill_kernel<<<(N_EDGES + 255) / 256, 256>>>();

    const int gatherBlocks = (int)(((long long)N_NODES * 32 + 255) / 256);
    const int gemmBlocks = (N_NODES + 127) / 128;

    int ins[4]  = {0, 1, 2, 1};
    int outs[4] = {1, 2, 1, 2};
    for (int L = 0; L < 4; L++) {
        gather_kernel<<<gatherBlocks, 256>>>(x, ins[L]);
        gemm_fused_kernel<<<gemmBlocks, 256>>>(x, ins[L], outs[L],
                                               Wrel[L], Wroot[L], bias[L]);
    }

    pool_kernel<<<N_GRAPHS, 128>>>(x, 2);
    fc1_kernel<<<N_GRAPHS / 4, 256>>>(fcw, fcb);
    fc2_kernel<<<(N_GRAPHS * DOUT + 127) / 128, 128>>>(regw, regb, out);
}

// round 12
// speedup vs baseline: 4.1936x; 1.0119x over previous
#include <cuda_runtime.h>
#include <cuda_fp16.h>
#include <cstdint>

#define N_NODES 100000
#define N_EDGES 1600000
#define N_GRAPHS 2048
#define D 128
#define DFC 256
#define DOUT 8

#define SCAN_CHUNK 1024
#define SCAN_NB ((N_NODES + SCAN_CHUNK - 1) / SCAN_CHUNK)   // 98

#define SA 20     // A smem stride (floats): banks (20g+t)%32 all distinct
#define SB 136    // B smem stride (floats): banks (8t+g)%32 all distinct

// ---------------- scratch (static device globals; no allocation) ----------------
__device__ float  g_agg[(size_t)N_NODES * D];
__device__ float  g_hA[(size_t)N_NODES * D];
__device__ float  g_hB[(size_t)N_NODES * D];
__device__ __half g_x16[(size_t)N_NODES * D];
__device__ __half g_h16A[(size_t)N_NODES * D];
__device__ __half g_h16B[(size_t)N_NODES * D];
__device__ float  g_pool[(size_t)N_GRAPHS * D];
__device__ float  g_fc1[(size_t)N_GRAPHS * DFC];
__device__ int    g_src[N_EDGES];
__device__ int    g_dst[N_EDGES];
__device__ int    g_batch[N_NODES];
__device__ int    g_counts[N_NODES];          // zeroed by cudaMemsetAsync
__device__ int    g_row_ptr[N_NODES + 1];
__device__ int    g_cursor[N_NODES];
__device__ int    g_csr_src[N_EDGES];
__device__ int    g_blocksum[SCAN_NB];

__device__ __forceinline__ const float* pick_in(const float* x, int sel) {
    return sel == 0 ? x : (sel == 1 ? g_hA : g_hB);
}
__device__ __forceinline__ float* pick_out(int sel) {
    return sel == 1 ? g_hA : g_hB;
}
__device__ __forceinline__ const __half* pick_in16(int sel) {
    return sel == 0 ? g_x16 : (sel == 1 ? g_h16A : g_h16B);
}
__device__ __forceinline__ __half* pick_out16(int sel) {
    return sel == 1 ? g_h16A : g_h16B;
}

// ---------------- tf32 helpers ----------------
__device__ __forceinline__ uint32_t f2tf32(float v) {
    uint32_t r;
    asm("cvt.rna.tf32.f32 %0, %1;" : "=r"(r) : "f"(v));
    return r;
}

__device__ __forceinline__ void mma_tf32(float* c, const uint32_t* a,
                                         uint32_t b0, uint32_t b1) {
    asm("mma.sync.aligned.m16n8k8.row.col.f32.tf32.tf32.f32 "
        "{%0,%1,%2,%3},{%4,%5,%6,%7},{%8,%9},{%0,%1,%2,%3};"
        : "+f"(c[0]), "+f"(c[1]), "+f"(c[2]), "+f"(c[3])
        : "r"(a[0]), "r"(a[1]), "r"(a[2]), "r"(a[3]), "r"(b0), "r"(b1));
}

// ---------------- convert indices (self-detecting dtype) + per-dst counts ----------------
__device__ __forceinline__ int detect_is64(const void* ei) {
    const long long* p64 = (const long long*)ei;
    int ok = 1;
    #pragma unroll
    for (int i = 0; i < 16; i++) {
        long long v = __ldg(&p64[i]);
        if (v < 0 || v >= N_NODES) ok = 0;
    }
    return ok;
}

__global__ void convert_count_kernel(const void* ei, const void* batch) {
    int i = blockIdx.x * blockDim.x + threadIdx.x;
    int is64 = detect_is64(ei);
    if (i < N_EDGES) {
        int s, d;
        if (is64) {
            const long long* p = (const long long*)ei;
            s = (int)__ldg(&p[i]);
            d = (int)__ldg(&p[(size_t)N_EDGES + i]);
        } else {
            const int* p = (const int*)ei;
            s = __ldg(&p[i]);
            d = __ldg(&p[N_EDGES + i]);
        }
        g_src[i] = s;
        g_dst[i] = d;
        atomicAdd(&g_counts[d], 1);
    }
    if (i < N_NODES) {
        if (is64) g_batch[i] = (int)__ldg(&((const long long*)batch)[i]);
        else      g_batch[i] = __ldg(&((const int*)batch)[i]);
    }
}

// ---------------- x -> fp16 mirror ----------------
__global__ void convert_x16_kernel(const float* __restrict__ x) {
    int i = blockIdx.x * blockDim.x + threadIdx.x;
    if (i >= N_NODES * (D / 4)) return;
    float4 v = __ldg(reinterpret_cast<const float4*>(x) + i);
    __half2 h0 = __floats2half2_rn(v.x, v.y);
    __half2 h1 = __floats2half2_rn(v.z, v.w);
    uint2 u;
    u.x = *reinterpret_cast<uint32_t*>(&h0);
    u.y = *reinterpret_cast<uint32_t*>(&h1);
    reinterpret_cast<uint2*>(g_x16)[i] = u;
}

// ---------------- scan: counts -> row_ptr (exclusive) ----------------
__global__ void scan1_kernel() {
    __shared__ int sh[256];
    int b = blockIdx.x, t = threadIdx.x;
    int i0 = b * SCAN_CHUNK + t * 4;
    int s = 0;
    #pragma unroll
    for (int j = 0; j < 4; j++) {
        int i = i0 + j;
        if (i < N_NODES) s += g_counts[i];
    }
    sh[t] = s;
    __syncthreads();
    for (int off = 128; off > 0; off >>= 1) {
        if (t < off) sh[t] += sh[t + off];
        __syncthreads();
    }
    if (t == 0) g_blocksum[b] = sh[0];
}

__global__ void scan2_kernel() {
    __shared__ int sh[128];
    int t = threadIdx.x;
    int v = (t < SCAN_NB) ? g_blocksum[t] : 0;
    sh[t] = v;
    __syncthreads();
    #pragma unroll
    for (int off = 1; off < 128; off <<= 1) {
        int u = (t >= off) ? sh[t - off] : 0;
        __syncthreads();
        sh[t] += u;
        __syncthreads();
    }
    if (t < SCAN_NB) g_blocksum[t] = sh[t] - v;   // exclusive
    if (t == 127) g_row_ptr[N_NODES] = sh[127];
}

__global__ void scan3_kernel() {
    __shared__ int sh[256];
    int b = blockIdx.x, t = threadIdx.x;
    int i0 = b * SCAN_CHUNK + t * 4;
    int c[4];
    int tsum = 0;
    #pragma unroll
    for (int j = 0; j < 4; j++) {
        int i = i0 + j;
        c[j] = (i < N_NODES) ? g_counts[i] : 0;
        tsum += c[j];
    }
    sh[t] = tsum;
    __syncthreads();
    #pragma unroll
    for (int off = 1; off < 256; off <<= 1) {
        int v = (t >= off) ? sh[t - off] : 0;
        __syncthreads();
        sh[t] += v;
        __syncthreads();
    }
    int base = g_blocksum[b] + sh[t] - tsum;
    #pragma unroll
    for (int j = 0; j < 4; j++) {
        int i = i0 + j;
        if (i < N_NODES) {
            g_row_ptr[i] = base;
            g_cursor[i]  = base;
            base += c[j];
        }
    }
}

// ---------------- fill CSR ----------------
__global__ void fill_kernel() {
    int e = blockIdx.x * blockDim.x + threadIdx.x;
    if (e >= N_EDGES) return;
    int d = g_dst[e];
    int pos = atomicAdd(&g_cursor[d], 1);
    g_csr_src[pos] = g_src[e];
}

// ---------------- gather from fp16 mirror: agg fp32 ----------------
__device__ __forceinline__ void acc_h4(float4& acc, uint2 u) {
    __half2 p0 = *reinterpret_cast<const __half2*>(&u.x);
    __half2 p1 = *reinterpret_cast<const __half2*>(&u.y);
    float2 a = __half22float2(p0);
    float2 b = __half22float2(p1);
    acc.x += a.x; acc.y += a.y; acc.z += b.x; acc.w += b.y;
}

__global__ void gather_kernel(int sel_in) {
    long long idx = (long long)blockIdx.x * blockDim.x + threadIdx.x;
    int node = (int)(idx >> 5);
    if (node >= N_NODES) return;
    int lane = (int)(idx & 31);
    const __half* h = pick_in16(sel_in);
    const uint2* h8 = reinterpret_cast<const uint2*>(h);   // 32 uint2 per row
    int beg = g_row_ptr[node];
    int end = g_row_ptr[node + 1];
    float4 acc = make_float4(0.f, 0.f, 0.f, 0.f);
    int e = beg;
    for (; e + 4 <= end; e += 4) {
        int s0 = __ldg(&g_csr_src[e]);
        int s1 = __ldg(&g_csr_src[e + 1]);
        int s2 = __ldg(&g_csr_src[e + 2]);
        int s3 = __ldg(&g_csr_src[e + 3]);
        uint2 u0 = __ldg(&h8[(size_t)s0 * 32 + lane]);
        uint2 u1 = __ldg(&h8[(size_t)s1 * 32 + lane]);
        uint2 u2 = __ldg(&h8[(size_t)s2 * 32 + lane]);
        uint2 u3 = __ldg(&h8[(size_t)s3 * 32 + lane]);
        acc_h4(acc, u0); acc_h4(acc, u1); acc_h4(acc, u2); acc_h4(acc, u3);
    }
    for (; e < end; e++) {
        int s = __ldg(&g_csr_src[e]);
        uint2 u = __ldg(&h8[(size_t)s * 32 + lane]);
        acc_h4(acc, u);
    }
    reinterpret_cast<float4*>(g_agg)[(size_t)node * 32 + lane] = acc;
}

// ---------------- fused dual-GEMM via tf32 mma.sync ----------------
__device__ __forceinline__ void mma_pair(
    const uint32_t* __restrict__ As_, const uint32_t* __restrict__ Bs_,
    int kc, int warp_m, int warp_n, int g, int t, float acc[2][8][4])
{
    uint32_t afr[2][4];
    #pragma unroll
    for (int mt = 0; mt < 2; mt++) {
        int r0 = warp_m * 32 + mt * 16;
        afr[mt][0] = As_[(r0 + g) * SA + kc + t];
        afr[mt][1] = As_[(r0 + g + 8) * SA + kc + t];
        afr[mt][2] = As_[(r0 + g) * SA + kc + t + 4];
        afr[mt][3] = As_[(r0 + g + 8) * SA + kc + t + 4];
    }
    #pragma unroll
    for (int nt = 0; nt < 8; nt++) {
        int n0 = warp_n * 64 + nt * 8;
        uint32_t b0 = Bs_[(kc + t) * SB + n0 + g];
        uint32_t b1 = Bs_[(kc + t + 4) * SB + n0 + g];
        mma_tf32(acc[0][nt], afr[0], b0, b1);
        mma_tf32(acc[1][nt], afr[1], b0, b1);
    }
}

__global__ __launch_bounds__(256) void gemm_fused_kernel(
    const float* __restrict__ x, int sel_in, int sel_out,
    const float* __restrict__ Wrel, const float* __restrict__ Wroot,
    const float* __restrict__ bias)
{
    __shared__ uint32_t Aa[128 * SA];
    __shared__ uint32_t Ah[128 * SA];
    __shared__ uint32_t Br[16 * SB];
    __shared__ uint32_t Bo[16 * SB];

    const float* hin = pick_in(x, sel_in);
    float* hout = pick_out(sel_out);
    __half* hout16 = pick_out16(sel_out);

    int m0 = blockIdx.x * 128;
    int tid = threadIdx.x;
    int wid = tid >> 5;
    int lane = tid & 31;
    int warp_m = wid & 3;
    int warp_n = wid >> 2;
    int g = lane >> 2;
    int t = lane & 3;

    float acc[2][8][4];
    #pragma unroll
    for (int mt = 0; mt < 2; mt++)
        #pragma unroll
        for (int nt = 0; nt < 8; nt++)
            #pragma unroll
            for (int j = 0; j < 4; j++) acc[mt][nt][j] = 0.f;

    for (int k0 = 0; k0 < 128; k0 += 16) {
        #pragma unroll
        for (int i = 0; i < 2; i++) {
            int f = tid * 2 + i;
            int row = f >> 2;
            int c4 = f & 3;
            int gr = m0 + row;
            float4 va = make_float4(0.f, 0.f, 0.f, 0.f);
            float4 vh = make_float4(0.f, 0.f, 0.f, 0.f);
            if (gr < N_NODES) {
                va = *reinterpret_cast<const float4*>(g_agg + (size_t)gr * 128 + k0 + c4 * 4);
                vh = *reinterpret_cast<const float4*>(hin   + (size_t)gr * 128 + k0 + c4 * 4);
            }
            int base = row * SA + c4 * 4;
            Aa[base + 0] = f2tf32(va.x); Aa[base + 1] = f2tf32(va.y);
            Aa[base + 2] = f2tf32(va.z); Aa[base + 3] = f2tf32(va.w);
            Ah[base + 0] = f2tf32(vh.x); Ah[base + 1] = f2tf32(vh.y);
            Ah[base + 2] = f2tf32(vh.z); Ah[base + 3] = f2tf32(vh.w);
        }
        #pragma unroll
        for (int i = 0; i < 2; i++) {
            int f = tid * 2 + i;
            int kr = f >> 5;
            int c4 = f & 31;
            float4 vr = *reinterpret_cast<const float4*>(Wrel  + (size_t)(k0 + kr) * 128 + c4 * 4);
            float4 vo = *reinterpret_cast<const float4*>(Wroot + (size_t)(k0 + kr) * 128 + c4 * 4);
            int base = kr * SB + c4 * 4;
            Br[base + 0] = f2tf32(vr.x); Br[base + 1] = f2tf32(vr.y);
            Br[base + 2] = f2tf32(vr.z); Br[base + 3] = f2tf32(vr.w);
            Bo[base + 0] = f2tf32(vo.x); Bo[base + 1] = f2tf32(vo.y);
            Bo[base + 2] = f2tf32(vo.z); Bo[base + 3] = f2tf32(vo.w);
        }
        __syncthreads();

        #pragma unroll
        for (int kc = 0; kc < 16; kc += 8) {
            mma_pair(Aa, Br, kc, warp_m, warp_n, g, t, acc);
            mma_pair(Ah, Bo, kc, warp_m, warp_n, g, t, acc);
        }
        __syncthreads();
    }

    // epilogue: bias + relu + fp32 store + fp16 mirror store
    #pragma unroll
    for (int nt = 0; nt < 8; nt++) {
        int col = warp_n * 64 + nt * 8 + 2 * t;
        float b0 = __ldg(&bias[col]);
        float b1 = __ldg(&bias[col + 1]);
        #pragma unroll
        for (int mt = 0; mt < 2; mt++) {
            int row0 = m0 + warp_m * 32 + mt * 16 + g;
            if (row0 < N_NODES) {
                float lo = fmaxf(acc[mt][nt][0] + b0, 0.f);
                float hi = fmaxf(acc[mt][nt][1] + b1, 0.f);
                *reinterpret_cast<float2*>(&hout[(size_t)row0 * 128 + col]) =
                    make_float2(lo, hi);
                *reinterpret_cast<__half2*>(&hout16[(size_t)row0 * 128 + col]) =
                    __floats2half2_rn(lo, hi);
            }
            int row1 = row0 + 8;
            if (row1 < N_NODES) {
                float lo = fmaxf(acc[mt][nt][2] + b0, 0.f);
                float hi = fmaxf(acc[mt][nt][3] + b1, 0.f);
                *reinterpret_cast<float2*>(&hout[(size_t)row1 * 128 + col]) =
                    make_float2(lo, hi);
                *reinterpret_cast<__half2*>(&hout16[(size_t)row1 * 128 + col]) =
                    __floats2half2_rn(lo, hi);
            }
        }
    }
}

// ---------------- pool: sorted-batch segments, block per graph, no atomics ----------------
__device__ __forceinline__ int lower_bound_batch(int v) {
    int lo = 0, hi = N_NODES;
    while (lo < hi) {
        int m = (lo + hi) >> 1;
        if (g_batch[m] < v) lo = m + 1; else hi = m;
    }
    return lo;
}

__global__ __launch_bounds__(128) void pool_kernel(const float* __restrict__ x, int sel_in) {
    int g = blockIdx.x;
    int t = threadIdx.x;
    const float* h = pick_in(x, sel_in);
    int lo = lower_bound_batch(g);
    int hi = lower_bound_batch(g + 1);
    float acc = 0.f;
    for (int n = lo; n < hi; n++)
        acc += __ldg(&h[(size_t)n * 128 + t]);
    float cnt = (float)(hi - lo);
    g_pool[(size_t)g * 128 + t] = acc / fmaxf(cnt, 1.0f);
}

// ---------------- fc1: 4 graphs per block ----------------
__global__ __launch_bounds__(256) void fc1_kernel(
    const float* __restrict__ w, const float* __restrict__ b)
{
    __shared__ float p[4][128];
    int g0 = blockIdx.x * 4;
    int t = threadIdx.x;
    #pragma unroll
    for (int i = 0; i < 2; i++) {
        int f = t + i * 256;
        p[f >> 7][f & 127] = g_pool[(size_t)g0 * 128 + f];
    }
    __syncthreads();
    float acc0 = b[t], acc1 = b[t], acc2 = b[t], acc3 = b[t];
    #pragma unroll 4
    for (int k = 0; k < 128; k++) {
        float wv = __ldg(&w[(size_t)k * 256 + t]);
        acc0 = fmaf(p[0][k], wv, acc0);
        acc1 = fmaf(p[1][k], wv, acc1);
        acc2 = fmaf(p[2][k], wv, acc2);
        acc3 = fmaf(p[3][k], wv, acc3);
    }
    g_fc1[(size_t)(g0 + 0) * 256 + t] = acc0;
    g_fc1[(size_t)(g0 + 1) * 256 + t] = acc1;
    g_fc1[(size_t)(g0 + 2) * 256 + t] = acc2;
    g_fc1[(size_t)(g0 + 3) * 256 + t] = acc3;
}

// ---------------- fc2 ----------------
__global__ void fc2_kernel(const float* __restrict__ w, const float* __restrict__ b,
                           float* __restrict__ out)
{
    int idx = blockIdx.x * blockDim.x + threadIdx.x;
    if (idx >= N_GRAPHS * DOUT) return;
    int g = idx >> 3, o = idx & 7;
    float acc = b[o];
    #pragma unroll 8
    for (int k = 0; k < 256; k++)
        acc = fmaf(g_fc1[(size_t)g * 256 + k], __ldg(&w[k * 8 + o]), acc);
    out[idx] = acc;
}

// ---------------- launch ----------------
extern "C" void kernel_launch(void* const* d_in, const int* in_sizes, int n_in,
                              void* d_out, int out_size)
{
    const float* x = (const float*)d_in[0];
    const void* ei = d_in[1];
    const void* batch = d_in[2];
    const float* Wrel[4]  = {(const float*)d_in[3], (const float*)d_in[6],
                             (const float*)d_in[9], (const float*)d_in[12]};
    const float* Wroot[4] = {(const float*)d_in[4], (const float*)d_in[7],
                             (const float*)d_in[10], (const float*)d_in[13]};
    const float* bias[4]  = {(const float*)d_in[5], (const float*)d_in[8],
                             (const float*)d_in[11], (const float*)d_in[14]};
    const float* fcw = (const float*)d_in[15];
    const float* fcb = (const float*)d_in[16];
    const float* regw = (const float*)d_in[17];
    const float* regb = (const float*)d_in[18];
    float* out = (float*)d_out;

    void* countsPtr = nullptr;
    cudaGetSymbolAddress(&countsPtr, g_counts);
    cudaMemsetAsync(countsPtr, 0, N_NODES * sizeof(int));

    // CSR build + x fp16 mirror
    convert_count_kernel<<<(N_EDGES + 255) / 256, 256>>>(ei, batch);
    convert_x16_kernel<<<(N_NODES * (D / 4) + 255) / 256, 256>>>(x);
    scan1_kernel<<<SCAN_NB, 256>>>();
    scan2_kernel<<<1, 128>>>();
    scan3_kernel<<<SCAN_NB, 256>>>();
    fill_kernel<<<(N_EDGES + 255) / 256, 256>>>();

    const int gatherBlocks = (int)(((long long)N_NODES * 32 + 255) / 256);
    const int gemmBlocks = (N_NODES + 127) / 128;

    int ins[4]  = {0, 1, 2, 1};
    int outs[4] = {1, 2, 1, 2};
    for (int L = 0; L < 4; L++) {
        gather_kernel<<<gatherBlocks, 256>>>(ins[L]);
        gemm_fused_kernel<<<gemmBlocks, 256>>>(x, ins[L], outs[L],
                                               Wrel[L], Wroot[L], bias[L]);
    }

    pool_kernel<<<N_GRAPHS, 128>>>(x, 2);
    fc1_kernel<<<N_GRAPHS / 4, 256>>>(fcw, fcb);
    fc2_kernel<<<(N_GRAPHS * DOUT + 127) / 128, 128>>>(regw, regb, out);
}